// round 5
// baseline (speedup 1.0000x reference)
#include <cuda_runtime.h>
#include <cuda_fp16.h>

// BilateralSliceApply on GB300 — y-prefold into fp16 SMEM, conflict-free layout,
// single barrier per CTA, packed f32x2 accumulation.
// grid:  (4, 12, 8, 16, 16) f32
// guide: (4, 1024, 1024) f32
// image: (4, 3, 1024, 1024) f32
// out:   (4, 3, 1024, 1024) f32

#define GD 8
#define GH 16
#define GW 16
#define NC 12
#define W_IMG 1024
#define H_IMG 1024
#define GRID_PER_B (NC * GD * GH * GW)   // 24576
#define ROWS_PER_BLOCK 4

// fp16 SMEM layout, in half2 (uint) units:
//   cell (z,x): 6 half2 used, padded to 8 (32 B)
//   z-slice: 16 cells * 32 B = 512 B, padded to 528 B (132 half2)  ->  528 mod 128 = 16
//   => within an LDS phase (x,c uniform), each z hits a distinct 16-B bank group.
#define XU 8        // x-cell stride in half2 units
#define ZU 132      // z-slice stride in half2 units
#define ROW_U (GD * ZU)   // 1056 half2 per row buffer

__device__ __forceinline__ unsigned long long pack2(float v) {
    unsigned long long r;
    asm("mov.b64 %0, {%1, %1};" : "=l"(r) : "f"(v));
    return r;
}
__device__ __forceinline__ void unpack2(unsigned long long v, float &lo, float &hi) {
    asm("mov.b64 {%0, %1}, %2;" : "=f"(lo), "=f"(hi) : "l"(v));
}
// half2 (as uint) -> f32x2 fma into packed accumulator
__device__ __forceinline__ void fma2h(unsigned long long &acc, unsigned int h2,
                                      unsigned long long w2) {
    asm("{\n\t"
        ".reg .b16 l, h;\n\t"
        ".reg .f32 fl, fh;\n\t"
        ".reg .b64 v;\n\t"
        "mov.b32 {l, h}, %1;\n\t"
        "cvt.f32.f16 fl, l;\n\t"
        "cvt.f32.f16 fh, h;\n\t"
        "mov.b64 v, {fl, fh};\n\t"
        "fma.rn.f32x2 %0, v, %2, %0;\n\t"
        "}" : "+l"(acc) : "r"(h2), "l"(w2));
}

// one tap: 12 halves = uint4 (c0..c7) + uint2 (c8..c11).
// NOTE: inline function (not macro) so the .w member access is safe.
__device__ __forceinline__ void tap(const unsigned int* __restrict__ rowbuf, int off,
                                    float wgt,
                                    unsigned long long &a0, unsigned long long &a1,
                                    unsigned long long &a2, unsigned long long &a3,
                                    unsigned long long &a4, unsigned long long &a5) {
    const uint4* p  = reinterpret_cast<const uint4*>(rowbuf + off);
    const uint4  q  = p[0];
    const uint2  q2 = reinterpret_cast<const uint2*>(p)[2];
    const unsigned long long w2 = pack2(wgt);
    fma2h(a0, q.x,  w2); fma2h(a1, q.y,  w2);
    fma2h(a2, q.z,  w2); fma2h(a3, q.w,  w2);
    fma2h(a4, q2.x, w2); fma2h(a5, q2.y, w2);
}

__global__ void __launch_bounds__(256, 3) bsa_kernel(
    const float* __restrict__ grid,
    const float* __restrict__ guide,
    const float* __restrict__ image,
    float* __restrict__ out)
{
    __shared__ __align__(16) unsigned int sg2[ROWS_PER_BLOCK][ROW_U];

    const int b   = blockIdx.y;
    const int tid = threadIdx.x;

    const float* gb = grid  + b * GRID_PER_B;
    const float* gu = guide + b * (H_IMG * W_IMG);
    const float* im = image + b * 3 * (H_IMG * W_IMG);
    float*       ob = out   + b * 3 * (H_IMG * W_IMG);

    const int row0 = blockIdx.x * ROWS_PER_BLOCK;

    // ---- stage all 4 rows: y-prefold in fp32, store fp16 pairs ----
    #pragma unroll
    for (int r = 0; r < ROWS_PER_BLOCK; ++r) {
        const int y = row0 + r;
        const float gyv = ((float)y + 0.5f) * (16.0f / 1024.0f);
        const float fym = floorf(gyv - 0.5f);
        const float ty  = gyv - 0.5f - fym;
        const int   ify = (int)fym;
        const int   iy0 = min(max(ify, 0), GH - 1);
        const int   iy1 = min(max(ify + 1, 0), GH - 1);
        const float wy0 = 1.0f - ty, wy1 = ty;

        // 768 channel-pairs per row: p = (cp*8 + z)*16 + x
        #pragma unroll
        for (int t = 0; t < 3; ++t) {
            const int p  = tid + t * 256;
            const int cp = p >> 7;
            const int z  = (p >> 4) & 7;
            const int x  = p & 15;
            const float* g0 = gb + (2 * cp)     * (GD * GH * GW) + z * (GH * GW) + x;
            const float* g1 = gb + (2 * cp + 1) * (GD * GH * GW) + z * (GH * GW) + x;
            const float f0 = wy0 * g0[iy0 * GW] + wy1 * g0[iy1 * GW];
            const float f1 = wy0 * g1[iy0 * GW] + wy1 * g1[iy1 * GW];
            __half2 h = __floats2half2_rn(f0, f1);
            sg2[r][z * ZU + x * XU + cp] = *reinterpret_cast<unsigned int*>(&h);
        }
    }
    __syncthreads();   // the only barrier

    // ---- process 4 rows, barrier-free ----
    #pragma unroll 1
    for (int r = 0; r < ROWS_PER_BLOCK; ++r) {
        const int y = row0 + r;
        const unsigned int* rowbuf = sg2[r];

        const int x4  = tid;
        const int px0 = x4 << 2;

        const float4 g4 = reinterpret_cast<const float4*>(gu + y * W_IMG)[x4];
        const float4 r4 = reinterpret_cast<const float4*>(im + 0 * 1048576 + y * W_IMG)[x4];
        const float4 q4 = reinterpret_cast<const float4*>(im + 1 * 1048576 + y * W_IMG)[x4];
        const float4 b4 = reinterpret_cast<const float4*>(im + 2 * 1048576 + y * W_IMG)[x4];

        const float gv[4] = {g4.x, g4.y, g4.z, g4.w};
        const float rv[4] = {r4.x, r4.y, r4.z, r4.w};
        const float qv[4] = {q4.x, q4.y, q4.z, q4.w};
        const float bv[4] = {b4.x, b4.y, b4.z, b4.w};

        float oR[4], oG[4], oB[4];

        #pragma unroll
        for (int j = 0; j < 4; ++j) {
            // x interpolation
            const float gx  = ((float)(px0 + j) + 0.5f) * (16.0f / 1024.0f);
            const float fxm = floorf(gx - 0.5f);
            const float tx  = gx - 0.5f - fxm;
            const int   ifx = (int)fxm;
            const int   ix0 = min(max(ifx, 0), GW - 1);
            const int   ix1 = min(max(ifx + 1, 0), GW - 1);
            const float wx0 = 1.0f - tx, wx1 = tx;

            // z interpolation (guide-driven)
            const float gz  = gv[j] * 8.0f;
            const float fzm = floorf(gz - 0.5f);
            const float tz  = gz - 0.5f - fzm;
            const int   ifz = (int)fzm;
            const int   iz0 = min(max(ifz, 0), GD - 1);
            const int   iz1 = min(max(ifz + 1, 0), GD - 1);
            const float wz0 = 1.0f - tz, wz1 = tz;

            const int zo0 = iz0 * ZU, zo1 = iz1 * ZU;
            const int co0 = ix0 * XU, co1 = ix1 * XU;

            unsigned long long a0 = 0, a1 = 0, a2 = 0, a3 = 0, a4 = 0, a5 = 0;

            tap(rowbuf, zo0 + co0, wz0 * wx0, a0, a1, a2, a3, a4, a5);
            tap(rowbuf, zo0 + co1, wz0 * wx1, a0, a1, a2, a3, a4, a5);
            tap(rowbuf, zo1 + co0, wz1 * wx0, a0, a1, a2, a3, a4, a5);
            tap(rowbuf, zo1 + co1, wz1 * wx1, a0, a1, a2, a3, a4, a5);

            float c0, c1, c2, c3, c4, c5, c6, c7, c8, c9, c10, c11;
            unpack2(a0, c0, c1);
            unpack2(a1, c2, c3);
            unpack2(a2, c4, c5);
            unpack2(a3, c6, c7);
            unpack2(a4, c8, c9);
            unpack2(a5, c10, c11);

            const float R = rv[j], G = qv[j], Bc = bv[j];
            oR[j] = fmaf(c0, R, fmaf(c1, G, fmaf(c2,  Bc, c3)));
            oG[j] = fmaf(c4, R, fmaf(c5, G, fmaf(c6,  Bc, c7)));
            oB[j] = fmaf(c8, R, fmaf(c9, G, fmaf(c10, Bc, c11)));
        }

        reinterpret_cast<float4*>(ob + 0 * 1048576 + y * W_IMG)[x4] =
            make_float4(oR[0], oR[1], oR[2], oR[3]);
        reinterpret_cast<float4*>(ob + 1 * 1048576 + y * W_IMG)[x4] =
            make_float4(oG[0], oG[1], oG[2], oG[3]);
        reinterpret_cast<float4*>(ob + 2 * 1048576 + y * W_IMG)[x4] =
            make_float4(oB[0], oB[1], oB[2], oB[3]);
    }
}

extern "C" void kernel_launch(void* const* d_in, const int* in_sizes, int n_in,
                              void* d_out, int out_size)
{
    const float* grid  = nullptr;
    const float* guide = nullptr;
    const float* image = nullptr;
    for (int i = 0; i < n_in; ++i) {
        if (in_sizes[i] == 4 * GRID_PER_B)             grid  = (const float*)d_in[i];
        else if (in_sizes[i] == 4 * H_IMG * W_IMG)     guide = (const float*)d_in[i];
        else if (in_sizes[i] == 4 * 3 * H_IMG * W_IMG) image = (const float*)d_in[i];
    }
    float* out = (float*)d_out;

    dim3 gr(H_IMG / ROWS_PER_BLOCK, 4);   // 256 x 4 = 1024 blocks, 4 rows each
    bsa_kernel<<<gr, 256>>>(grid, guide, image, out);
}

// round 6
// speedup vs baseline: 1.1413x; 1.1413x over previous
#include <cuda_runtime.h>

// BilateralSliceApply on GB300 — y-prefold + conflict-free (z,x) fp32 SMEM layout.
// R6: same as R3 but 4 CTAs/SM (64-reg cap) for latency hiding.
// grid:  (4, 12, 8, 16, 16) f32
// guide: (4, 1024, 1024) f32
// image: (4, 3, 1024, 1024) f32
// out:   (4, 3, 1024, 1024) f32

#define GD 8
#define GH 16
#define GW 16
#define NC 12
#define W_IMG 1024
#define H_IMG 1024
#define GRID_PER_B (NC * GD * GH * GW)   // 24576
#define XS 16                             // x-stride in floats (64 B cell)
#define ZS 260                            // z-stride in floats (1040 B; 1040 mod 128 = 16)
#define GY_SZ (GD * ZS)                   // 2080 floats per buffer
#define ROWS_PER_BLOCK 4

__device__ __forceinline__ unsigned long long pack2(float v) {
    unsigned long long r;
    asm("mov.b64 %0, {%1, %1};" : "=l"(r) : "f"(v));
    return r;
}
__device__ __forceinline__ void fma2(unsigned long long &acc, unsigned long long a,
                                     unsigned long long w) {
    asm("fma.rn.f32x2 %0, %1, %2, %0;" : "+l"(acc) : "l"(a), "l"(w));
}
__device__ __forceinline__ void unpack2(unsigned long long v, float &lo, float &hi) {
    asm("mov.b64 {%0, %1}, %2;" : "=f"(lo), "=f"(hi) : "l"(v));
}

// one tap: 12 floats = 3x LDS.128 viewed as packed f32x2 pairs
__device__ __forceinline__ void tap(const float* __restrict__ buf, int off, float wgt,
                                    unsigned long long &a0, unsigned long long &a1,
                                    unsigned long long &a2, unsigned long long &a3,
                                    unsigned long long &a4, unsigned long long &a5) {
    const ulonglong2* p = reinterpret_cast<const ulonglong2*>(buf + off);
    const unsigned long long w2 = pack2(wgt);
    ulonglong2 q0 = p[0];
    ulonglong2 q1 = p[1];
    ulonglong2 q2 = p[2];
    fma2(a0, q0.x, w2); fma2(a1, q0.y, w2);
    fma2(a2, q1.x, w2); fma2(a3, q1.y, w2);
    fma2(a4, q2.x, w2); fma2(a5, q2.y, w2);
}

__global__ void __launch_bounds__(256, 4) bsa_kernel(
    const float* __restrict__ grid,
    const float* __restrict__ guide,
    const float* __restrict__ image,
    float* __restrict__ out)
{
    __shared__ __align__(16) float gybuf[2][GY_SZ];

    const int b   = blockIdx.y;
    const int tid = threadIdx.x;

    const float* gb = grid  + b * GRID_PER_B;
    const float* gu = guide + b * (H_IMG * W_IMG);
    const float* im = image + b * 3 * (H_IMG * W_IMG);
    float*       ob = out   + b * 3 * (H_IMG * W_IMG);

    const int row0 = blockIdx.x * ROWS_PER_BLOCK;

    for (int k = 0; k < ROWS_PER_BLOCK; ++k) {
        const int y = row0 + k;

        // ---- per-row y interpolation state ----
        const float gyv = ((float)y + 0.5f) * (16.0f / 1024.0f);
        const float fym = floorf(gyv - 0.5f);
        const float ty  = gyv - 0.5f - fym;
        const int   ify = (int)fym;
        const int   iy0 = min(max(ify, 0), GH - 1);
        const int   iy1 = min(max(ify + 1, 0), GH - 1);
        const float wy0 = 1.0f - ty, wy1 = ty;

        float* buf = gybuf[k & 1];

        // ---- stage y-prefolded grid row: 1536 values, 6 per thread ----
        // i = ((c*8)+z)*16 + x -> consecutive threads read consecutive x (coalesced)
        #pragma unroll
        for (int t = 0; t < 6; ++t) {
            const int i = tid + t * 256;            // [0, 1536)
            const int c = i >> 7;                   // /128
            const int z = (i >> 4) & 7;
            const int x = i & 15;
            const float* gp = gb + c * (GD * GH * GW) + z * (GH * GW) + x;
            buf[z * ZS + x * XS + c] = wy0 * gp[iy0 * GW] + wy1 * gp[iy1 * GW];
        }
        __syncthreads();   // double buffer separates row k reads from row k+2 writes

        // ---- process this row: thread tid owns float4 group x4 = tid ----
        const int x4  = tid;
        const int px0 = x4 << 2;

        const float4 g4 = reinterpret_cast<const float4*>(gu + y * W_IMG)[x4];
        const float4 r4 = reinterpret_cast<const float4*>(im + 0 * 1048576 + y * W_IMG)[x4];
        const float4 q4 = reinterpret_cast<const float4*>(im + 1 * 1048576 + y * W_IMG)[x4];
        const float4 b4 = reinterpret_cast<const float4*>(im + 2 * 1048576 + y * W_IMG)[x4];

        float4 outR, outG, outB;

        #pragma unroll
        for (int j = 0; j < 4; ++j) {
            const float gvj = (j == 0) ? g4.x : (j == 1) ? g4.y : (j == 2) ? g4.z : g4.w;
            const float R   = (j == 0) ? r4.x : (j == 1) ? r4.y : (j == 2) ? r4.z : r4.w;
            const float G   = (j == 0) ? q4.x : (j == 1) ? q4.y : (j == 2) ? q4.z : q4.w;
            const float Bc  = (j == 0) ? b4.x : (j == 1) ? b4.y : (j == 2) ? b4.z : b4.w;

            // x interpolation
            const float gx  = ((float)(px0 + j) + 0.5f) * (16.0f / 1024.0f);
            const float fxm = floorf(gx - 0.5f);
            const float tx  = gx - 0.5f - fxm;
            const int   ifx = (int)fxm;
            const int   ix0 = min(max(ifx, 0), GW - 1);
            const int   ix1 = min(max(ifx + 1, 0), GW - 1);
            const float wx0 = 1.0f - tx, wx1 = tx;

            // z interpolation (guide-driven)
            const float gz  = gvj * 8.0f;
            const float fzm = floorf(gz - 0.5f);
            const float tz  = gz - 0.5f - fzm;
            const int   ifz = (int)fzm;
            const int   iz0 = min(max(ifz, 0), GD - 1);
            const int   iz1 = min(max(ifz + 1, 0), GD - 1);
            const float wz0 = 1.0f - tz, wz1 = tz;

            const int zo0 = iz0 * ZS, zo1 = iz1 * ZS;
            const int co0 = ix0 * XS, co1 = ix1 * XS;

            unsigned long long a0 = 0, a1 = 0, a2 = 0, a3 = 0, a4 = 0, a5 = 0;

            tap(buf, zo0 + co0, wz0 * wx0, a0, a1, a2, a3, a4, a5);
            tap(buf, zo0 + co1, wz0 * wx1, a0, a1, a2, a3, a4, a5);
            tap(buf, zo1 + co0, wz1 * wx0, a0, a1, a2, a3, a4, a5);
            tap(buf, zo1 + co1, wz1 * wx1, a0, a1, a2, a3, a4, a5);

            float c0, c1, c2, c3, c4, c5, c6, c7, c8, c9, c10, c11;
            unpack2(a0, c0, c1);
            unpack2(a1, c2, c3);
            unpack2(a2, c4, c5);
            unpack2(a3, c6, c7);
            unpack2(a4, c8, c9);
            unpack2(a5, c10, c11);

            const float vR = fmaf(c0, R, fmaf(c1, G, fmaf(c2,  Bc, c3)));
            const float vG = fmaf(c4, R, fmaf(c5, G, fmaf(c6,  Bc, c7)));
            const float vB = fmaf(c8, R, fmaf(c9, G, fmaf(c10, Bc, c11)));

            if (j == 0)      { outR.x = vR; outG.x = vG; outB.x = vB; }
            else if (j == 1) { outR.y = vR; outG.y = vG; outB.y = vB; }
            else if (j == 2) { outR.z = vR; outG.z = vG; outB.z = vB; }
            else             { outR.w = vR; outG.w = vG; outB.w = vB; }
        }

        reinterpret_cast<float4*>(ob + 0 * 1048576 + y * W_IMG)[x4] = outR;
        reinterpret_cast<float4*>(ob + 1 * 1048576 + y * W_IMG)[x4] = outG;
        reinterpret_cast<float4*>(ob + 2 * 1048576 + y * W_IMG)[x4] = outB;
    }
}

extern "C" void kernel_launch(void* const* d_in, const int* in_sizes, int n_in,
                              void* d_out, int out_size)
{
    const float* grid  = nullptr;
    const float* guide = nullptr;
    const float* image = nullptr;
    for (int i = 0; i < n_in; ++i) {
        if (in_sizes[i] == 4 * GRID_PER_B)             grid  = (const float*)d_in[i];
        else if (in_sizes[i] == 4 * H_IMG * W_IMG)     guide = (const float*)d_in[i];
        else if (in_sizes[i] == 4 * 3 * H_IMG * W_IMG) image = (const float*)d_in[i];
    }
    float* out = (float*)d_out;

    dim3 gr(H_IMG / ROWS_PER_BLOCK, 4);   // 256 x 4 = 1024 blocks, 4 rows each
    bsa_kernel<<<gr, 256>>>(grid, guide, image, out);
}

// round 7
// speedup vs baseline: 1.1445x; 1.0028x over previous
#include <cuda_runtime.h>

// BilateralSliceApply on GB300 — R7: strided pixel->lane mapping makes every
// LDS phase x-uniform => fully conflict-free taps; staging stride XS=20 cuts
// STS conflicts 8-way -> 2-way.
// grid:  (4, 12, 8, 16, 16) f32
// guide: (4, 1024, 1024) f32
// image: (4, 3, 1024, 1024) f32
// out:   (4, 3, 1024, 1024) f32

#define GD 8
#define GH 16
#define GW 16
#define NC 12
#define W_IMG 1024
#define H_IMG 1024
#define GRID_PER_B (NC * GD * GH * GW)   // 24576
#define XS 20                             // x-cell stride in floats (80 B, 16B-aligned)
#define ZS 324                            // z-stride in floats (1296 B; 324/4=81 ≡ 1 mod 8)
#define GY_SZ (GD * ZS)                   // 2592 floats per buffer (10.4 KB)
#define ROWS_PER_BLOCK 4

__device__ __forceinline__ unsigned long long pack2(float v) {
    unsigned long long r;
    asm("mov.b64 %0, {%1, %1};" : "=l"(r) : "f"(v));
    return r;
}
__device__ __forceinline__ void fma2(unsigned long long &acc, unsigned long long a,
                                     unsigned long long w) {
    asm("fma.rn.f32x2 %0, %1, %2, %0;" : "+l"(acc) : "l"(a), "l"(w));
}
__device__ __forceinline__ void unpack2(unsigned long long v, float &lo, float &hi) {
    asm("mov.b64 {%0, %1}, %2;" : "=f"(lo), "=f"(hi) : "l"(v));
}

// one tap: 12 floats = 3x LDS.128 viewed as packed f32x2 pairs
__device__ __forceinline__ void tap(const float* __restrict__ buf, int off, float wgt,
                                    unsigned long long &a0, unsigned long long &a1,
                                    unsigned long long &a2, unsigned long long &a3,
                                    unsigned long long &a4, unsigned long long &a5) {
    const ulonglong2* p = reinterpret_cast<const ulonglong2*>(buf + off);
    const unsigned long long w2 = pack2(wgt);
    ulonglong2 q0 = p[0];
    ulonglong2 q1 = p[1];
    ulonglong2 q2 = p[2];
    fma2(a0, q0.x, w2); fma2(a1, q0.y, w2);
    fma2(a2, q1.x, w2); fma2(a3, q1.y, w2);
    fma2(a4, q2.x, w2); fma2(a5, q2.y, w2);
}

__global__ void __launch_bounds__(256, 4) bsa_kernel(
    const float* __restrict__ grid,
    const float* __restrict__ guide,
    const float* __restrict__ image,
    float* __restrict__ out)
{
    __shared__ __align__(16) float gybuf[2][GY_SZ];

    const int b   = blockIdx.y;
    const int tid = threadIdx.x;

    const float* gb = grid  + b * GRID_PER_B;
    const float* gu = guide + b * (H_IMG * W_IMG);
    const float* im = image + b * 3 * (H_IMG * W_IMG);
    float*       ob = out   + b * 3 * (H_IMG * W_IMG);

    const int row0 = blockIdx.x * ROWS_PER_BLOCK;

    for (int k = 0; k < ROWS_PER_BLOCK; ++k) {
        const int y = row0 + k;

        // ---- per-row y interpolation state ----
        const float gyv = ((float)y + 0.5f) * (16.0f / 1024.0f);
        const float fym = floorf(gyv - 0.5f);
        const float ty  = gyv - 0.5f - fym;
        const int   ify = (int)fym;
        const int   iy0 = min(max(ify, 0), GH - 1);
        const int   iy1 = min(max(ify + 1, 0), GH - 1);
        const float wy0 = 1.0f - ty, wy1 = ty;

        float* buf = gybuf[k & 1];

        // ---- stage y-prefolded grid row: 1536 values, 6 per thread ----
        // i = ((c*8)+z)*16 + x -> consecutive threads read consecutive x (coalesced LDG)
        // STS banks: (4z + 20x + c) mod 32, 20x has period 8 over x -> 2-way max
        #pragma unroll
        for (int t = 0; t < 6; ++t) {
            const int i = tid + t * 256;            // [0, 1536)
            const int c = i >> 7;                   // /128
            const int z = (i >> 4) & 7;
            const int x = i & 15;
            const float* gp = gb + c * (GD * GH * GW) + z * (GH * GW) + x;
            buf[z * ZS + x * XS + c] = wy0 * gp[iy0 * GW] + wy1 * gp[iy1 * GW];
        }
        __syncthreads();   // double buffer separates row k reads from row k+2 writes

        // ---- process this row: lane tid owns pixels tid + 256*j (j=0..3) ----
        // 8-lane LDS phases span 8 consecutive pixels -> x-cell uniform per phase
        // -> tap group index (z + const) mod 8 distinct per z -> conflict-free.
        #pragma unroll
        for (int j = 0; j < 4; ++j) {
            const int px = tid + (j << 8);

            const float gvj = gu[y * W_IMG + px];
            const float R   = im[0 * 1048576 + y * W_IMG + px];
            const float G   = im[1 * 1048576 + y * W_IMG + px];
            const float Bc  = im[2 * 1048576 + y * W_IMG + px];

            // x interpolation
            const float gx  = ((float)px + 0.5f) * (16.0f / 1024.0f);
            const float fxm = floorf(gx - 0.5f);
            const float tx  = gx - 0.5f - fxm;
            const int   ifx = (int)fxm;
            const int   ix0 = min(max(ifx, 0), GW - 1);
            const int   ix1 = min(max(ifx + 1, 0), GW - 1);
            const float wx0 = 1.0f - tx, wx1 = tx;

            // z interpolation (guide-driven)
            const float gz  = gvj * 8.0f;
            const float fzm = floorf(gz - 0.5f);
            const float tz  = gz - 0.5f - fzm;
            const int   ifz = (int)fzm;
            const int   iz0 = min(max(ifz, 0), GD - 1);
            const int   iz1 = min(max(ifz + 1, 0), GD - 1);
            const float wz0 = 1.0f - tz, wz1 = tz;

            const int zo0 = iz0 * ZS, zo1 = iz1 * ZS;
            const int co0 = ix0 * XS, co1 = ix1 * XS;

            unsigned long long a0 = 0, a1 = 0, a2 = 0, a3 = 0, a4 = 0, a5 = 0;

            tap(buf, zo0 + co0, wz0 * wx0, a0, a1, a2, a3, a4, a5);
            tap(buf, zo0 + co1, wz0 * wx1, a0, a1, a2, a3, a4, a5);
            tap(buf, zo1 + co0, wz1 * wx0, a0, a1, a2, a3, a4, a5);
            tap(buf, zo1 + co1, wz1 * wx1, a0, a1, a2, a3, a4, a5);

            float c0, c1, c2, c3, c4, c5, c6, c7, c8, c9, c10, c11;
            unpack2(a0, c0, c1);
            unpack2(a1, c2, c3);
            unpack2(a2, c4, c5);
            unpack2(a3, c6, c7);
            unpack2(a4, c8, c9);
            unpack2(a5, c10, c11);

            ob[0 * 1048576 + y * W_IMG + px] = fmaf(c0, R, fmaf(c1, G, fmaf(c2,  Bc, c3)));
            ob[1 * 1048576 + y * W_IMG + px] = fmaf(c4, R, fmaf(c5, G, fmaf(c6,  Bc, c7)));
            ob[2 * 1048576 + y * W_IMG + px] = fmaf(c8, R, fmaf(c9, G, fmaf(c10, Bc, c11)));
        }
    }
}

extern "C" void kernel_launch(void* const* d_in, const int* in_sizes, int n_in,
                              void* d_out, int out_size)
{
    const float* grid  = nullptr;
    const float* guide = nullptr;
    const float* image = nullptr;
    for (int i = 0; i < n_in; ++i) {
        if (in_sizes[i] == 4 * GRID_PER_B)             grid  = (const float*)d_in[i];
        else if (in_sizes[i] == 4 * H_IMG * W_IMG)     guide = (const float*)d_in[i];
        else if (in_sizes[i] == 4 * 3 * H_IMG * W_IMG) image = (const float*)d_in[i];
    }
    float* out = (float*)d_out;

    dim3 gr(H_IMG / ROWS_PER_BLOCK, 4);   // 256 x 4 = 1024 blocks, 4 rows each
    bsa_kernel<<<gr, 256>>>(grid, guide, image, out);
}

// round 8
// speedup vs baseline: 1.6656x; 1.4554x over previous
#include <cuda_runtime.h>
#include <cuda_fp16.h>

// BilateralSliceApply on GB300 — R8: fp16 grid in SMEM consumed natively with
// HFMA2 (fp16 accumulate over the 4 taps), single fp32 conversion at epilogue.
// Strided pixel->lane mapping (R7) keeps every LDS phase x-uniform -> no conflicts.
// grid:  (4, 12, 8, 16, 16) f32
// guide: (4, 1024, 1024) f32
// image: (4, 3, 1024, 1024) f32
// out:   (4, 3, 1024, 1024) f32

#define GD 8
#define GH 16
#define GW 16
#define NC 12
#define W_IMG 1024
#define H_IMG 1024
#define GRID_PER_B (NC * GD * GH * GW)   // 24576
#define ROWS_PER_BLOCK 4

// fp16 SMEM layout in half2 (uint) units:
//   cell (z,x): 6 half2 used, padded to 8 (32 B)     -> XU = 8
//   z-slice: 16 cells * 32 B = 512 B + 16 B pad = 528 B (132 uints) -> ZU = 132
//   528 mod 128 = 16  =>  distinct 16-B bank group per z within an x-uniform phase.
#define XU 8
#define ZU 132
#define ROW_U (GD * ZU)   // 1056 uints per row buffer (4224 B)

__device__ __forceinline__ __half2 u2h(unsigned int u) {
    __half2 h;
    *reinterpret_cast<unsigned int*>(&h) = u;
    return h;
}

// one tap: 12 halves = uint4 (c0..c7) + uint2 (c8..c11), hfma2 into 6 fp16 accumulators
__device__ __forceinline__ void taph(const unsigned int* __restrict__ buf, int off,
                                     __half2 w2, __half2* acc) {
    const uint4 q  = *reinterpret_cast<const uint4*>(buf + off);
    const uint2 q2 = *reinterpret_cast<const uint2*>(buf + off + 4);
    acc[0] = __hfma2(u2h(q.x),  w2, acc[0]);
    acc[1] = __hfma2(u2h(q.y),  w2, acc[1]);
    acc[2] = __hfma2(u2h(q.z),  w2, acc[2]);
    acc[3] = __hfma2(u2h(q.w),  w2, acc[3]);
    acc[4] = __hfma2(u2h(q2.x), w2, acc[4]);
    acc[5] = __hfma2(u2h(q2.y), w2, acc[5]);
}

__global__ void __launch_bounds__(256, 4) bsa_kernel(
    const float* __restrict__ grid,
    const float* __restrict__ guide,
    const float* __restrict__ image,
    float* __restrict__ out)
{
    __shared__ __align__(16) unsigned int sg2[ROWS_PER_BLOCK][ROW_U];

    const int b   = blockIdx.y;
    const int tid = threadIdx.x;

    const float* gb = grid  + b * GRID_PER_B;
    const float* gu = guide + b * (H_IMG * W_IMG);
    const float* im = image + b * 3 * (H_IMG * W_IMG);
    float*       ob = out   + b * 3 * (H_IMG * W_IMG);

    const int row0 = blockIdx.x * ROWS_PER_BLOCK;

    // ---- stage all 4 rows: y-prefold in fp32, store fp16 pairs; one barrier ----
    #pragma unroll
    for (int r = 0; r < ROWS_PER_BLOCK; ++r) {
        const int y = row0 + r;
        const float gyv = ((float)y + 0.5f) * (16.0f / 1024.0f);
        const float fym = floorf(gyv - 0.5f);
        const float ty  = gyv - 0.5f - fym;
        const int   ify = (int)fym;
        const int   iy0 = min(max(ify, 0), GH - 1);
        const int   iy1 = min(max(ify + 1, 0), GH - 1);
        const float wy0 = 1.0f - ty, wy1 = ty;

        // 768 channel-pairs per row: p = (cp*8 + z)*16 + x  (coalesced LDG over x)
        #pragma unroll
        for (int t = 0; t < 3; ++t) {
            const int p  = tid + t * 256;
            const int cp = p >> 7;
            const int z  = (p >> 4) & 7;
            const int x  = p & 15;
            const float* g0 = gb + (2 * cp)     * (GD * GH * GW) + z * (GH * GW) + x;
            const float* g1 = gb + (2 * cp + 1) * (GD * GH * GW) + z * (GH * GW) + x;
            const float f0 = wy0 * g0[iy0 * GW] + wy1 * g0[iy1 * GW];
            const float f1 = wy0 * g1[iy0 * GW] + wy1 * g1[iy1 * GW];
            __half2 h = __floats2half2_rn(f0, f1);
            sg2[r][z * ZU + x * XU + cp] = *reinterpret_cast<unsigned int*>(&h);
        }
    }
    __syncthreads();   // the only barrier

    // ---- process rows; lane tid owns pixels tid + 256*j ----
    #pragma unroll 1
    for (int r = 0; r < ROWS_PER_BLOCK; ++r) {
        const int y = row0 + r;
        const unsigned int* rowbuf = sg2[r];

        #pragma unroll
        for (int j = 0; j < 4; ++j) {
            const int px = tid + (j << 8);

            const float gvj = gu[y * W_IMG + px];
            const float R   = im[0 * 1048576 + y * W_IMG + px];
            const float G   = im[1 * 1048576 + y * W_IMG + px];
            const float Bc  = im[2 * 1048576 + y * W_IMG + px];

            // x interpolation
            const float gx  = ((float)px + 0.5f) * (16.0f / 1024.0f);
            const float fxm = floorf(gx - 0.5f);
            const float tx  = gx - 0.5f - fxm;
            const int   ifx = (int)fxm;
            const int   ix0 = min(max(ifx, 0), GW - 1);
            const int   ix1 = min(max(ifx + 1, 0), GW - 1);
            const float wx0 = 1.0f - tx, wx1 = tx;

            // z interpolation (guide-driven)
            const float gz  = gvj * 8.0f;
            const float fzm = floorf(gz - 0.5f);
            const float tz  = gz - 0.5f - fzm;
            const int   ifz = (int)fzm;
            const int   iz0 = min(max(ifz, 0), GD - 1);
            const int   iz1 = min(max(ifz + 1, 0), GD - 1);
            const float wz0 = 1.0f - tz, wz1 = tz;

            const int zo0 = iz0 * ZU, zo1 = iz1 * ZU;
            const int co0 = ix0 * XU, co1 = ix1 * XU;

            __half2 acc[6];
            acc[0] = acc[1] = acc[2] = acc[3] = acc[4] = acc[5] =
                __half2half2(__ushort_as_half(0));

            taph(rowbuf, zo0 + co0, __float2half2_rn(wz0 * wx0), acc);
            taph(rowbuf, zo0 + co1, __float2half2_rn(wz0 * wx1), acc);
            taph(rowbuf, zo1 + co0, __float2half2_rn(wz1 * wx0), acc);
            taph(rowbuf, zo1 + co1, __float2half2_rn(wz1 * wx1), acc);

            const float2 p0 = __half22float2(acc[0]);
            const float2 p1 = __half22float2(acc[1]);
            const float2 p2 = __half22float2(acc[2]);
            const float2 p3 = __half22float2(acc[3]);
            const float2 p4 = __half22float2(acc[4]);
            const float2 p5 = __half22float2(acc[5]);

            ob[0 * 1048576 + y * W_IMG + px] =
                fmaf(p0.x, R, fmaf(p0.y, G, fmaf(p1.x, Bc, p1.y)));
            ob[1 * 1048576 + y * W_IMG + px] =
                fmaf(p2.x, R, fmaf(p2.y, G, fmaf(p3.x, Bc, p3.y)));
            ob[2 * 1048576 + y * W_IMG + px] =
                fmaf(p4.x, R, fmaf(p4.y, G, fmaf(p5.x, Bc, p5.y)));
        }
    }
}

extern "C" void kernel_launch(void* const* d_in, const int* in_sizes, int n_in,
                              void* d_out, int out_size)
{
    const float* grid  = nullptr;
    const float* guide = nullptr;
    const float* image = nullptr;
    for (int i = 0; i < n_in; ++i) {
        if (in_sizes[i] == 4 * GRID_PER_B)             grid  = (const float*)d_in[i];
        else if (in_sizes[i] == 4 * H_IMG * W_IMG)     guide = (const float*)d_in[i];
        else if (in_sizes[i] == 4 * 3 * H_IMG * W_IMG) image = (const float*)d_in[i];
    }
    float* out = (float*)d_out;

    dim3 gr(H_IMG / ROWS_PER_BLOCK, 4);   // 256 x 4 = 1024 blocks, 4 rows each
    bsa_kernel<<<gr, 256>>>(grid, guide, image, out);
}